// round 1
// baseline (speedup 1.0000x reference)
#include <cuda_runtime.h>
#include <cuda_bf16.h>

// ---------------------------------------------------------------------------
// DeformableMNIST: x(256,1,28,28)
//  off1 = conv3x3(x, off_w1)+off_b1            (256,18,28,28)
//  h1   = deform_conv(x, off1, w1, b1)         (256,32,28,28)
//  p1   = maxpool2(relu(h1))                   (256,32,14,14)   [channel-last]
//  off2 = conv3x3(p1, off_w2)+off_b2           (256,18,14,14)   [channel-last]
//  h2   = deform_conv(p1, off2, w2, b2)        (256,64,14,14)
//  p2   = maxpool2(relu(h2))                   (256,64,7,7)
//  out  = p2.flat @ fc_w.T + fc_b              (256,10)
// ---------------------------------------------------------------------------

#define BMAX 256

// scratch (channel-last where noted)
__device__ float g_p1t [BMAX * 14 * 14 * 32];   // (b, h, w, c)
__device__ float g_off2t[BMAX * 14 * 14 * 18];  // (b, h, w, c)
__device__ float g_w2t [288 * 64];              // [kk*32+ci][o]
__device__ float g_p2  [BMAX * 64 * 7 * 7];     // standard (b, c, h, w)

// bilinear corner sample, zero padding semantics (valid-mask * clipped-gather)
__device__ __forceinline__ float corner(const float* __restrict__ p,
                                        int y, int x, int H, int W, int stride) {
    bool v = (y >= 0) & (y < H) & (x >= 0) & (x < W);
    int yc = min(max(y, 0), H - 1);
    int xc = min(max(x, 0), W - 1);
    return v ? p[(yc * W + xc) * stride] : 0.f;
}

// ---------------------------------------------------------------------------
// Kernel 1: fused offset-conv(1->18) + deform-conv(1->32) + relu + maxpool2.
// One thread per pooled output pixel (b, h2, w2); computes 4 input pixels.
// Writes p1 channel-last.
// ---------------------------------------------------------------------------
__global__ void __launch_bounds__(128)
k_stage1(const float* __restrict__ x,
         const float* __restrict__ ow, const float* __restrict__ ob,
         const float* __restrict__ w1, const float* __restrict__ b1, int B) {
    int idx = blockIdx.x * blockDim.x + threadIdx.x;
    if (idx >= B * 14 * 14) return;
    int w2i = idx % 14;
    int t   = idx / 14;
    int h2i = t % 14;
    int b   = t / 14;
    const float* xb = x + b * 784;

    // 3x3 input patches for the 4 pooled pixels
    float xp[4][9];
#pragma unroll
    for (int p = 0; p < 4; p++) {
        int h = h2i * 2 + (p >> 1), w = w2i * 2 + (p & 1);
#pragma unroll
        for (int tt = 0; tt < 9; tt++) {
            int yy = h + tt / 3 - 1, xx = w + tt % 3 - 1;
            xp[p][tt] = (yy >= 0 && yy < 28 && xx >= 0 && xx < 28) ? xb[yy * 28 + xx] : 0.f;
        }
    }

    // per-tap offsets + bilinear sample (weights loaded once per kk, reused x4 pixels)
    float samp[4][9];
#pragma unroll
    for (int kk = 0; kk < 9; kk++) {
        float wr0[9], wr1[9];
#pragma unroll
        for (int tt = 0; tt < 9; tt++) {
            wr0[tt] = ow[(2 * kk) * 9 + tt];
            wr1[tt] = ow[(2 * kk + 1) * 9 + tt];
        }
        float bdy = ob[2 * kk], bdx = ob[2 * kk + 1];
        int iy = kk / 3 - 1, ix = kk % 3 - 1;
#pragma unroll
        for (int p = 0; p < 4; p++) {
            float dy = bdy, dx = bdx;
#pragma unroll
            for (int tt = 0; tt < 9; tt++) {
                dy = fmaf(wr0[tt], xp[p][tt], dy);
                dx = fmaf(wr1[tt], xp[p][tt], dx);
            }
            int h = h2i * 2 + (p >> 1), w = w2i * 2 + (p & 1);
            float py = (float)(h + iy) + dy;
            float px = (float)(w + ix) + dx;
            float fy = floorf(py), fx = floorf(px);
            float ay = py - fy, ax = px - fx;
            int y0 = (int)fy, x0 = (int)fx;
            float v00 = corner(xb, y0,     x0,     28, 28, 1);
            float v01 = corner(xb, y0,     x0 + 1, 28, 28, 1);
            float v10 = corner(xb, y0 + 1, x0,     28, 28, 1);
            float v11 = corner(xb, y0 + 1, x0 + 1, 28, 28, 1);
            samp[p][kk] = (1.f - ay) * ((1.f - ax) * v00 + ax * v01)
                        +         ay * ((1.f - ax) * v10 + ax * v11);
        }
    }

    // 32 output channels: dot + bias, pool(max of 4), relu. weights loaded once per oc.
    float* o = g_p1t + (b * 196 + h2i * 14 + w2i) * 32;
#pragma unroll
    for (int oc = 0; oc < 32; oc++) {
        float wv[9];
#pragma unroll
        for (int kk = 0; kk < 9; kk++) wv[kk] = w1[oc * 9 + kk];
        float m = -1e30f;
#pragma unroll
        for (int p = 0; p < 4; p++) {
            float a = b1[oc];
#pragma unroll
            for (int kk = 0; kk < 9; kk++) a = fmaf(wv[kk], samp[p][kk], a);
            m = fmaxf(m, a);
        }
        o[oc] = fmaxf(m, 0.f);
    }
}

// ---------------------------------------------------------------------------
// Kernel 2: offset conv 2 (32 -> 18 channels, 14x14, pad 1).
// One thread per pixel PAIR along w (2 pixels share every weight load).
// Reads p1 channel-last (vectorized float4), writes off2 channel-last.
// ---------------------------------------------------------------------------
__global__ void __launch_bounds__(128)
k_offconv2(const float* __restrict__ ow, const float* __restrict__ ob, int B) {
    int idx = blockIdx.x * blockDim.x + threadIdx.x;
    if (idx >= B * 14 * 7) return;
    int wp = idx % 7;
    int t  = idx / 7;
    int h  = t % 14;
    int b  = t / 14;
    int w0 = wp * 2;

    float acc[2][18];
#pragma unroll
    for (int c = 0; c < 18; c++) { acc[0][c] = ob[c]; acc[1][c] = ob[c]; }

    const float* pb = g_p1t + b * 196 * 32;

    for (int tt = 0; tt < 9; tt++) {
        int y  = h + tt / 3 - 1;
        int dx = tt % 3 - 1;
        int x0 = w0 + dx, x1 = w0 + 1 + dx;
        bool yok = (y >= 0) & (y < 14);
        bool ok0 = yok & (x0 >= 0) & (x0 < 14);
        bool ok1 = yok & (x1 >= 0) & (x1 < 14);
        const float* p0 = pb + (y * 14 + x0) * 32;
        const float* p1 = pb + (y * 14 + x1) * 32;

        for (int cib = 0; cib < 4; cib++) {
            float v0[8], v1[8];
            if (ok0) {
                float4 a = *(const float4*)(p0 + cib * 8);
                float4 c4 = *(const float4*)(p0 + cib * 8 + 4);
                v0[0] = a.x; v0[1] = a.y; v0[2] = a.z; v0[3] = a.w;
                v0[4] = c4.x; v0[5] = c4.y; v0[6] = c4.z; v0[7] = c4.w;
            } else {
#pragma unroll
                for (int q = 0; q < 8; q++) v0[q] = 0.f;
            }
            if (ok1) {
                float4 a = *(const float4*)(p1 + cib * 8);
                float4 c4 = *(const float4*)(p1 + cib * 8 + 4);
                v1[0] = a.x; v1[1] = a.y; v1[2] = a.z; v1[3] = a.w;
                v1[4] = c4.x; v1[5] = c4.y; v1[6] = c4.z; v1[7] = c4.w;
            } else {
#pragma unroll
                for (int q = 0; q < 8; q++) v1[q] = 0.f;
            }
#pragma unroll
            for (int c = 0; c < 18; c++) {
#pragma unroll
                for (int q = 0; q < 8; q++) {
                    float wv = ow[(c * 32 + cib * 8 + q) * 9 + tt];
                    acc[0][c] = fmaf(wv, v0[q], acc[0][c]);
                    acc[1][c] = fmaf(wv, v1[q], acc[1][c]);
                }
            }
        }
    }

    float* o = g_off2t + (b * 196 + h * 14 + w0) * 18;
#pragma unroll
    for (int c = 0; c < 18; c++) { o[c] = acc[0][c]; o[18 + c] = acc[1][c]; }
}

// ---------------------------------------------------------------------------
// Kernel 3: transpose w2 (64,32,3,3) -> [kk*32+ci][o] for coalesced phase-2 loads
// ---------------------------------------------------------------------------
__global__ void k_transpose_w2(const float* __restrict__ w2) {
    int i = blockIdx.x * blockDim.x + threadIdx.x;
    if (i >= 64 * 288) return;
    int o = i / 288, r = i % 288, ci = r / 9, kk = r % 9;
    g_w2t[(kk * 32 + ci) * 64 + o] = w2[i];
}

// ---------------------------------------------------------------------------
// Kernel 4: deform conv 2 (288 -> 64) + relu + maxpool2, fused.
// Block = one pooled output pixel (b,h3,w3); 64 threads.
// Phase 1: stage 4x288 bilinear samples in SMEM (lane = channel -> coalesced,
//          warp covers exactly one kk -> uniform coords / broadcast offsets).
// Phase 2: thread o = output channel; coalesced w2t loads, broadcast LDS.
// ---------------------------------------------------------------------------
__global__ void __launch_bounds__(64)
k_deform2(const float* __restrict__ b2, int B) {
    __shared__ float samp_s[1152];
    int blk = blockIdx.x;
    int w3 = blk % 7;
    int t  = blk / 7;
    int h3 = t % 7;
    int b  = t / 7;
    int tid = threadIdx.x;

    const float* pbase = g_p1t + b * 196 * 32;

#pragma unroll
    for (int i = 0; i < 18; i++) {
        int e  = tid + i * 64;            // e = p*288 + kk*32 + ci
        int p  = e / 288;
        int r  = e % 288;
        int kk = r / 32;
        int ci = r % 32;
        int h = h3 * 2 + (p >> 1), w = w3 * 2 + (p & 1);
        const float* od = g_off2t + (b * 196 + h * 14 + w) * 18;
        float dy = od[2 * kk], dx = od[2 * kk + 1];
        float py = (float)(h + kk / 3 - 1) + dy;
        float px = (float)(w + kk % 3 - 1) + dx;
        float fy = floorf(py), fx = floorf(px);
        float ay = py - fy, ax = px - fx;
        int y0 = (int)fy, x0 = (int)fx;
        const float* pc = pbase + ci;
        float v00 = corner(pc, y0,     x0,     14, 14, 32);
        float v01 = corner(pc, y0,     x0 + 1, 14, 14, 32);
        float v10 = corner(pc, y0 + 1, x0,     14, 14, 32);
        float v11 = corner(pc, y0 + 1, x0 + 1, 14, 14, 32);
        samp_s[e] = (1.f - ay) * ((1.f - ax) * v00 + ax * v01)
                  +         ay * ((1.f - ax) * v10 + ax * v11);
    }
    __syncthreads();

    int o = tid;
    float a0 = b2[o], a1 = a0, a2 = a0, a3 = a0;
    const float* wt = g_w2t + o;
#pragma unroll 8
    for (int s = 0; s < 288; s++) {
        float wv = wt[s * 64];
        a0 = fmaf(wv, samp_s[s],       a0);
        a1 = fmaf(wv, samp_s[288 + s], a1);
        a2 = fmaf(wv, samp_s[576 + s], a2);
        a3 = fmaf(wv, samp_s[864 + s], a3);
    }
    float m = fmaxf(fmaxf(a0, a1), fmaxf(a2, a3));
    g_p2[(b * 64 + o) * 49 + h3 * 7 + w3] = fmaxf(m, 0.f);
}

// ---------------------------------------------------------------------------
// Kernel 5: FC (256,3136) @ (10,3136)^T + bias. One warp per (b, oc).
// ---------------------------------------------------------------------------
__global__ void __launch_bounds__(320)
k_fc(const float* __restrict__ fw, const float* __restrict__ fb,
     float* __restrict__ out, int B) {
    int b = blockIdx.x;
    int warp = threadIdx.x >> 5;
    int lane = threadIdx.x & 31;
    const float* row = g_p2 + b * 3136;
    const float* wr  = fw + warp * 3136;
    float s = 0.f;
    for (int i = lane * 4; i < 3136; i += 128) {
        float4 a = *(const float4*)(row + i);
        float4 w = *(const float4*)(wr + i);
        s += a.x * w.x + a.y * w.y + a.z * w.z + a.w * w.w;
    }
#pragma unroll
    for (int off = 16; off; off >>= 1) s += __shfl_xor_sync(0xffffffffu, s, off);
    if (lane == 0) out[b * 10 + warp] = s + fb[warp];
}

// ---------------------------------------------------------------------------
extern "C" void kernel_launch(void* const* d_in, const int* in_sizes, int n_in,
                              void* d_out, int out_size) {
    const float* x      = (const float*)d_in[0];
    const float* off_w1 = (const float*)d_in[1];
    const float* off_b1 = (const float*)d_in[2];
    const float* w1     = (const float*)d_in[3];
    const float* b1     = (const float*)d_in[4];
    const float* off_w2 = (const float*)d_in[5];
    const float* off_b2 = (const float*)d_in[6];
    const float* w2     = (const float*)d_in[7];
    const float* b2     = (const float*)d_in[8];
    const float* fc_w   = (const float*)d_in[9];
    const float* fc_b   = (const float*)d_in[10];
    float* out = (float*)d_out;

    int B = in_sizes[0] / 784;
    if (B > BMAX) B = BMAX;

    k_transpose_w2<<<(64 * 288 + 255) / 256, 256>>>(w2);
    k_stage1<<<(B * 196 + 127) / 128, 128>>>(x, off_w1, off_b1, w1, b1, B);
    k_offconv2<<<(B * 98 + 127) / 128, 128>>>(off_w2, off_b2, B);
    k_deform2<<<B * 49, 64>>>(b2, B);
    k_fc<<<B, 320>>>(fc_w, fc_b, out, B);
}